// round 14
// baseline (speedup 1.0000x reference)
#include <cuda_runtime.h>
#include <cuda_fp16.h>
#include <cstdint>
#include <math.h>

#define BATCH 4
#define SEQ 2048
#define CH 768
#define NHEADS 12
#define HD 64
#define MTOT (BATCH * SEQ)   // 8192
#define C3 (3 * CH)          // 2304
#define KSCALE (0.125f * 1.44269504089f)   // 1/sqrt(d) * log2(e)

// Scratch (allocation-free contract) — all fp16 (weights K-major now)
__device__ __half g_x[(size_t)MTOT * CH];
__device__ __half g_qkv[(size_t)MTOT * C3];
__device__ __half g_att[(size_t)MTOT * CH];
__device__ __half g_wqkvH[(size_t)CH * C3];    // [K=768][N=2304], Q-cols scaled
__device__ __half g_wprojH[(size_t)CH * CH];   // [K=768][N=768]
__device__ float  g_bqkvS[C3];                 // bias, Q-part scaled

__device__ __forceinline__ uint32_t smem_u32(const void* p) {
    uint32_t a;
    asm("{ .reg .u64 t; cvta.to.shared.u64 t, %1; cvt.u32.u64 %0, t; }"
        : "=r"(a) : "l"(p));
    return a;
}
#define CP16(dst, src) \
    asm volatile("cp.async.cg.shared.global [%0], [%1], 16;" \
                 :: "r"(dst), "l"(src) : "memory")
#define CP_COMMIT() asm volatile("cp.async.commit_group;" ::: "memory")
#define CP_WAIT(n)  asm volatile("cp.async.wait_group %0;" :: "n"(n) : "memory")

// m16n8k16 fp16 mma, fp32 accumulate in-place.
__device__ __forceinline__ void mma16(float* c, const unsigned* a,
                                      unsigned b0, unsigned b1) {
    asm volatile(
        "mma.sync.aligned.m16n8k16.row.col.f32.f16.f16.f32 "
        "{%0,%1,%2,%3}, {%4,%5,%6,%7}, {%8,%9}, {%0,%1,%2,%3};"
        : "+f"(c[0]), "+f"(c[1]), "+f"(c[2]), "+f"(c[3])
        : "r"(a[0]), "r"(a[1]), "r"(a[2]), "r"(a[3]), "r"(b0), "r"(b1));
}
__device__ __forceinline__ void ldsm4(unsigned& r0, unsigned& r1,
                                      unsigned& r2, unsigned& r3,
                                      uint32_t addr) {
    asm volatile("ldmatrix.sync.aligned.m8n8.x4.shared.b16 {%0,%1,%2,%3}, [%4];"
                 : "=r"(r0), "=r"(r1), "=r"(r2), "=r"(r3) : "r"(addr));
}
__device__ __forceinline__ void ldsm4t(unsigned& r0, unsigned& r1,
                                       unsigned& r2, unsigned& r3,
                                       uint32_t addr) {
    asm volatile("ldmatrix.sync.aligned.m8n8.x4.trans.shared.b16 {%0,%1,%2,%3}, [%4];"
                 : "=r"(r0), "=r"(r1), "=r"(r2), "=r"(r3) : "r"(addr));
}
__device__ __forceinline__ unsigned packh2(float a, float b) {
    __half2 h = __floats2half2_rn(a, b);
    return *(unsigned*)&h;
}
__device__ __forceinline__ unsigned ex2h2(unsigned x) {
    unsigned r;
    asm("ex2.approx.f16x2 %0, %1;" : "=r"(r) : "r"(x));
    return r;
}
__device__ __forceinline__ float2 h2f2(unsigned x) {
    __half2 h = *(__half2*)&x;
    return __half22float2(h);
}

// ---------------------------------------------------------------------------
// Prepass: round x to fp16 (vectorized)
// ---------------------------------------------------------------------------
__global__ __launch_bounds__(256) void round_kernel(
    const float* __restrict__ in, __half* __restrict__ outp)
{
    const int idx = blockIdx.x * 256 + threadIdx.x;
    float4 v = ((const float4*)in)[idx];
    __half2 h0 = __floats2half2_rn(v.x, v.y);
    __half2 h1 = __floats2half2_rn(v.z, v.w);
    uint2 o = { *(unsigned*)&h0, *(unsigned*)&h1 };
    ((uint2*)outp)[idx] = o;
}

// ---------------------------------------------------------------------------
// Weight round (K-major kept), first scale_cols columns scaled.
// Grid: (ncols/256, nrows), block 256.
// ---------------------------------------------------------------------------
__global__ __launch_bounds__(256) void wround_kernel(
    const float* __restrict__ W, __half* __restrict__ Wh,
    int ncols, int scale_cols, float scale)
{
    const int n = blockIdx.x * 256 + threadIdx.x;
    const long i = (long)blockIdx.y * ncols + n;
    float v = W[i];
    if (n < scale_cols) v *= scale;
    Wh[i] = __float2half_rn(v);
}

__global__ void bscale_kernel(const float* __restrict__ b,
                              float* __restrict__ outp)
{
    const int idx = blockIdx.x * 256 + threadIdx.x;
    if (idx < C3) outp[idx] = b[idx] * (idx < CH ? KSCALE : 1.f);
}

// ---------------------------------------------------------------------------
// fp16 mma.sync GEMM + bias: C[M,N] = A[M,K] @ B[K,N] + bias
// B is K-MAJOR [K][N] fp16; B-fragments via ldmatrix.trans (flash-V pattern).
// 128x128 CTA tile, BK=64, 256 threads, 2-stage cp.async, 2 CTAs/SM.
// A smem stride 72 halves; B smem tile [64 k][128 n] stride 136 halves.
// ---------------------------------------------------------------------------
#define HS 72
#define BS 136
#define ASTG (128 * HS)          // halves
#define BSTG (64 * BS)           // halves
#define STGH (ASTG + BSTG)       // halves per stage (17920)

template <bool HALF_OUT>
__global__ __launch_bounds__(256, 2) void gemm_fp16(
    const __half* __restrict__ A, const __half* __restrict__ B,
    const float* __restrict__ bias, void* __restrict__ Cout,
    int M, int N, int K)
{
    extern __shared__ __half hsm[];
    const int tid = threadIdx.x;
    const int lane = tid & 31, wid = tid >> 5;
    const int g = lane >> 2, tq = lane & 3;
    const int wm = (wid & 3) * 32, wn = (wid >> 2) * 64;
    const int bm = blockIdx.y * 128, bn = blockIdx.x * 128;
    const int ar = tid >> 3, ac8 = (tid & 7) * 8;    // A staging map
    const int br = tid >> 4, bc8 = (tid & 15) * 8;   // B staging map

    const uint32_t sbase = smem_u32(hsm);
    const uint32_t a_base0 = sbase +
        ((wm + (lane & 15)) * HS + (lane >> 4) * 8) * 2;
    // trans-B frag: k-row (lane&7)+((lane>>3)&1)*8, n-col wn + (lane>>4)*8
    const uint32_t b_base0 = sbase + ASTG * 2 +
        (((lane & 7) + ((lane >> 3) & 1) * 8) * BS + wn + (lane >> 4) * 8) * 2;

    float acc[2][8][4];
    #pragma unroll
    for (int mt = 0; mt < 2; mt++)
        #pragma unroll
        for (int nt = 0; nt < 8; nt++)
            #pragma unroll
            for (int j = 0; j < 4; j++) acc[mt][nt][j] = 0.f;

    const int NK = K / 64;
    auto issue = [&](int kt, int st) {
        __half* As = hsm + st * STGH;
        __half* Bs = As + ASTG;
        const int k0 = kt * 64;
        #pragma unroll
        for (int i = 0; i < 4; i++) {               // A: 128 rows x 8 chunks
            int r = ar + 32 * i;
            CP16(smem_u32(As + r * HS + ac8),
                 A + (long)(bm + r) * K + k0 + ac8);
        }
        #pragma unroll
        for (int i = 0; i < 4; i++) {               // B: 64 k-rows x 16 chunks
            int r = br + 16 * i;
            CP16(smem_u32(Bs + r * BS + bc8),
                 B + (long)(k0 + r) * N + bn + bc8);
        }
        CP_COMMIT();
    };

    issue(0, 0);
    for (int kt = 0; kt < NK; kt++) {
        const int buf = kt & 1;
        if (kt + 1 < NK) { issue(kt + 1, buf ^ 1); CP_WAIT(1); }
        else             { CP_WAIT(0); }
        __syncthreads();

        const uint32_t a_buf = a_base0 + buf * STGH * 2;
        const uint32_t b_buf = b_base0 + buf * STGH * 2;
        #pragma unroll
        for (int ks = 0; ks < 4; ks++) {
            unsigned af[2][4];
            ldsm4(af[0][0], af[0][1], af[0][2], af[0][3], a_buf + ks * 32);
            ldsm4(af[1][0], af[1][1], af[1][2], af[1][3],
                  a_buf + 16 * HS * 2 + ks * 32);
            #pragma unroll
            for (int p = 0; p < 4; p++) {
                unsigned b0, b1, c0, c1;
                ldsm4t(b0, b1, c0, c1,
                       b_buf + ks * 16 * BS * 2 + p * 16 * 2);
                mma16(acc[0][2 * p],     af[0], b0, b1);
                mma16(acc[1][2 * p],     af[1], b0, b1);
                mma16(acc[0][2 * p + 1], af[0], c0, c1);
                mma16(acc[1][2 * p + 1], af[1], c0, c1);
            }
        }
        __syncthreads();
    }

    #pragma unroll
    for (int mt = 0; mt < 2; mt++) {
        const long r0 = bm + wm + mt * 16 + g;
        #pragma unroll
        for (int nt = 0; nt < 8; nt++) {
            const int col = bn + wn + nt * 8 + 2 * tq;
            const float bz0 = bias[col], bz1 = bias[col + 1];
            if (HALF_OUT) {
                __half* C = (__half*)Cout;
                __half2 v0 = __floats2half2_rn(acc[mt][nt][0] + bz0,
                                               acc[mt][nt][1] + bz1);
                __half2 v1 = __floats2half2_rn(acc[mt][nt][2] + bz0,
                                               acc[mt][nt][3] + bz1);
                *(__half2*)(C + r0 * N + col)       = v0;
                *(__half2*)(C + (r0 + 8) * N + col) = v1;
            } else {
                float* C = (float*)Cout;
                float2 v0 = { acc[mt][nt][0] + bz0, acc[mt][nt][1] + bz1 };
                float2 v1 = { acc[mt][nt][2] + bz0, acc[mt][nt][3] + bz1 };
                *(float2*)(C + r0 * N + col)       = v0;
                *(float2*)(C + (r0 + 8) * N + col) = v1;
            }
        }
    }
}

// ---------------------------------------------------------------------------
// Flash attention fp16 (R13 config; Q pre-scaled in qkv so staging is pure
// cp.async): Br=128, Bc=64, 128 threads (4 warps), 3 CTAs/SM, 2-stage KV,
// P in registers, ex2.approx.f16x2 softmax, deferred l reduction.
// Smem (halves, stride 72): Q 128 | K 2x64 | V 2x64 = 55296 B.
// ---------------------------------------------------------------------------
#define QS_OFF 0
#define KS_OFF (128 * HS)
#define VS_OFF (128 * HS + 2 * 64 * HS)
#define KVBUF (64 * HS)
#define FL_HALVES (128 * HS + 4 * 64 * HS)   // 27648 halves = 55296 B
#define NTILES (SEQ / 64)                    // 32

__global__ __launch_bounds__(128, 3) void flash_fp16()
{
    extern __shared__ __half fsm[];
    __half* Qs = fsm + QS_OFF;

    const int tid = threadIdx.x;
    const int lane = tid & 31, w = tid >> 5;
    const int g = lane >> 2, tq = lane & 3;
    const int b = blockIdx.y / NHEADS, h = blockIdx.y % NHEADS;
    const int q0 = blockIdx.x * 128;
    const long rowbase = (long)b * SEQ;

    const uint32_t q_base = smem_u32(Qs) +
        ((w * 32 + (lane & 15)) * HS + (lane >> 4) * 8) * 2;
    const uint32_t k_base = smem_u32(fsm + KS_OFF) +
        (((lane & 7) + (lane >> 4) * 8) * HS + ((lane >> 3) & 1) * 8) * 2;
    const uint32_t v_base = smem_u32(fsm + VS_OFF) +
        (((lane & 7) + ((lane >> 3) & 1) * 8) * HS + (lane >> 4) * 8) * 2;

    // Stage Q: pure cp.async (Q already scaled by KSCALE in the QKV GEMM)
    #pragma unroll
    for (int i = 0; i < 8; i++) {
        int idx = tid + 128 * i;
        int r = idx >> 3, c8 = (idx & 7) * 8;
        CP16(smem_u32(Qs + r * HS + c8),
             &g_qkv[(rowbase + q0 + r) * C3 + h * HD + c8]);
    }
    CP_COMMIT();

    auto issue_kv = [&](int t, int bf) {
        __half* Kd = fsm + KS_OFF + bf * KVBUF;
        __half* Vd = fsm + VS_OFF + bf * KVBUF;
        const int k0 = t * 64;
        #pragma unroll
        for (int i = 0; i < 4; i++) {
            int idx = tid + 128 * i;
            int r = idx >> 3, c8 = (idx & 7) * 8;
            long gb = (rowbase + k0 + r) * C3 + h * HD + c8;
            CP16(smem_u32(Kd + r * HS + c8), &g_qkv[gb + CH]);
            CP16(smem_u32(Vd + r * HS + c8), &g_qkv[gb + 2 * CH]);
        }
        CP_COMMIT();
    };

    float o[2][8][4];
    float m_i[2][2], l_p[2][2];
    #pragma unroll
    for (int mt = 0; mt < 2; mt++) {
        m_i[mt][0] = m_i[mt][1] = -1e30f;
        l_p[mt][0] = l_p[mt][1] = 0.f;
        #pragma unroll
        for (int nt = 0; nt < 8; nt++)
            #pragma unroll
            for (int j = 0; j < 4; j++) o[mt][nt][j] = 0.f;
    }

    issue_kv(0, 0);
    for (int t = 0; t < NTILES; t++) {
        const int buf = t & 1;
        CP_WAIT(0);
        __syncthreads();
        if (t + 1 < NTILES) issue_kv(t + 1, buf ^ 1);

        const uint32_t k_buf = k_base + buf * KVBUF * 2;
        const uint32_t v_buf = v_base + buf * KVBUF * 2;

        // S = Q @ K^T
        float s[2][8][4];
        #pragma unroll
        for (int mt = 0; mt < 2; mt++)
            #pragma unroll
            for (int nt = 0; nt < 8; nt++)
                #pragma unroll
                for (int j = 0; j < 4; j++) s[mt][nt][j] = 0.f;
        #pragma unroll
        for (int ks = 0; ks < 4; ks++) {
            unsigned af[2][4];
            ldsm4(af[0][0], af[0][1], af[0][2], af[0][3], q_base + ks * 32);
            ldsm4(af[1][0], af[1][1], af[1][2], af[1][3],
                  q_base + 16 * HS * 2 + ks * 32);
            #pragma unroll
            for (int p = 0; p < 4; p++) {
                unsigned b0, b1, c0, c1;
                ldsm4(b0, b1, c0, c1, k_buf + p * 16 * HS * 2 + ks * 32);
                mma16(s[0][2 * p],     af[0], b0, b1);
                mma16(s[1][2 * p],     af[1], b0, b1);
                mma16(s[0][2 * p + 1], af[0], c0, c1);
                mma16(s[1][2 * p + 1], af[1], c0, c1);
            }
        }

        // Online softmax (base-2): half2-packed ex2 writes PV A-frags.
        unsigned pa[2][4][4];
        #pragma unroll
        for (int mt = 0; mt < 2; mt++) {
            float mx0 = -1e30f, mx1 = -1e30f;
            #pragma unroll
            for (int nt = 0; nt < 8; nt++) {
                mx0 = fmaxf(mx0, fmaxf(s[mt][nt][0], s[mt][nt][1]));
                mx1 = fmaxf(mx1, fmaxf(s[mt][nt][2], s[mt][nt][3]));
            }
            mx0 = fmaxf(mx0, __shfl_xor_sync(0xffffffffu, mx0, 1));
            mx0 = fmaxf(mx0, __shfl_xor_sync(0xffffffffu, mx0, 2));
            mx1 = fmaxf(mx1, __shfl_xor_sync(0xffffffffu, mx1, 1));
            mx1 = fmaxf(mx1, __shfl_xor_sync(0xffffffffu, mx1, 2));
            const float mn0 = fmaxf(m_i[mt][0], mx0), mn1 = fmaxf(m_i[mt][1], mx1);
            const float cr0 = exp2f(m_i[mt][0] - mn0), cr1 = exp2f(m_i[mt][1] - mn1);
            float rs0 = 0.f, rs1 = 0.f;
            #pragma unroll
            for (int j = 0; j < 4; j++) {
                unsigned e0 = ex2h2(packh2(s[mt][2*j][0]   - mn0,
                                           s[mt][2*j][1]   - mn0));
                unsigned e1 = ex2h2(packh2(s[mt][2*j][2]   - mn1,
                                           s[mt][2*j][3]   - mn1));
                unsigned e2 = ex2h2(packh2(s[mt][2*j+1][0] - mn0,
                                           s[mt][2*j+1][1] - mn0));
                unsigned e3 = ex2h2(packh2(s[mt][2*j+1][2] - mn1,
                                           s[mt][2*j+1][3] - mn1));
                pa[mt][j][0] = e0; pa[mt][j][1] = e1;
                pa[mt][j][2] = e2; pa[mt][j][3] = e3;
                float2 f0 = h2f2(e0), f1 = h2f2(e1);
                float2 f2 = h2f2(e2), f3 = h2f2(e3);
                rs0 += (f0.x + f0.y) + (f2.x + f2.y);
                rs1 += (f1.x + f1.y) + (f3.x + f3.y);
            }
            l_p[mt][0] = l_p[mt][0] * cr0 + rs0;
            l_p[mt][1] = l_p[mt][1] * cr1 + rs1;
            m_i[mt][0] = mn0; m_i[mt][1] = mn1;
            #pragma unroll
            for (int nt = 0; nt < 8; nt++) {
                o[mt][nt][0] *= cr0; o[mt][nt][1] *= cr0;
                o[mt][nt][2] *= cr1; o[mt][nt][3] *= cr1;
            }
        }

        // O += P @ V
        #pragma unroll
        for (int ks = 0; ks < 4; ks++) {
            #pragma unroll
            for (int p = 0; p < 4; p++) {
                unsigned b0, b1, c0, c1;
                ldsm4t(b0, b1, c0, c1,
                       v_buf + ks * 16 * HS * 2 + p * 16 * 2);
                mma16(o[0][2 * p],     pa[0][ks], b0, b1);
                mma16(o[1][2 * p],     pa[1][ks], b0, b1);
                mma16(o[0][2 * p + 1], pa[0][ks], c0, c1);
                mma16(o[1][2 * p + 1], pa[1][ks], c0, c1);
            }
        }
    }

    // Epilogue: quad-reduce l partials, normalize, store fp16.
    #pragma unroll
    for (int mt = 0; mt < 2; mt++) {
        float l0 = l_p[mt][0], l1 = l_p[mt][1];
        l0 += __shfl_xor_sync(0xffffffffu, l0, 1);
        l0 += __shfl_xor_sync(0xffffffffu, l0, 2);
        l1 += __shfl_xor_sync(0xffffffffu, l1, 1);
        l1 += __shfl_xor_sync(0xffffffffu, l1, 2);
        const float inv0 = 1.f / l0, inv1 = 1.f / l1;
        const long r0 = rowbase + q0 + w * 32 + mt * 16 + g;
        #pragma unroll
        for (int nt = 0; nt < 8; nt++) {
            const int col = h * HD + nt * 8 + 2 * tq;
            *(__half2*)(g_att + r0 * CH + col) =
                __floats2half2_rn(o[mt][nt][0] * inv0, o[mt][nt][1] * inv0);
            *(__half2*)(g_att + (r0 + 8) * CH + col) =
                __floats2half2_rn(o[mt][nt][2] * inv1, o[mt][nt][3] * inv1);
        }
    }
}

// ---------------------------------------------------------------------------
extern "C" void kernel_launch(void* const* d_in, const int* in_sizes, int n_in,
                              void* d_out, int out_size)
{
    const float* x     = (const float*)d_in[0];
    const float* Wqkv  = (const float*)d_in[1];
    const float* bqkv  = (const float*)d_in[2];
    const float* Wproj = (const float*)d_in[3];
    const float* bproj = (const float*)d_in[4];
    float* out = (float*)d_out;

    __half *xr, *qkv_ptr, *att_ptr, *wqkvH, *wprojH;
    float* bqkvS;
    cudaGetSymbolAddress((void**)&xr, g_x);
    cudaGetSymbolAddress((void**)&qkv_ptr, g_qkv);
    cudaGetSymbolAddress((void**)&att_ptr, g_att);
    cudaGetSymbolAddress((void**)&wqkvH, g_wqkvH);
    cudaGetSymbolAddress((void**)&wprojH, g_wprojH);
    cudaGetSymbolAddress((void**)&bqkvS, g_bqkvS);

    static int smem_set = 0;
    const int gemm_smem  = 2 * STGH * sizeof(__half);    // 71680 B
    const int flash_smem = FL_HALVES * sizeof(__half);   // 55296 B
    if (!smem_set) {
        cudaFuncSetAttribute(gemm_fp16<true>,
            cudaFuncAttributeMaxDynamicSharedMemorySize, gemm_smem);
        cudaFuncSetAttribute(gemm_fp16<false>,
            cudaFuncAttributeMaxDynamicSharedMemorySize, gemm_smem);
        cudaFuncSetAttribute(flash_fp16,
            cudaFuncAttributeMaxDynamicSharedMemorySize, flash_smem);
        smem_set = 1;
    }

    // Prepasses: x -> fp16; weights -> fp16 K-major (Q-cols of Wqkv scaled);
    // bias Q-part scaled.
    round_kernel<<<(MTOT * CH) / 1024, 256>>>(x, xr);
    wround_kernel<<<dim3(C3 / 256, CH), 256>>>(Wqkv, wqkvH, C3, CH, KSCALE);
    wround_kernel<<<dim3(CH / 256, CH), 256>>>(Wproj, wprojH, CH, 0, 1.f);
    bscale_kernel<<<(C3 + 255) / 256, 256>>>(bqkv, bqkvS);

    // QKV projection (fp16 output; Q portion pre-scaled)
    gemm_fp16<true><<<dim3(C3 / 128, MTOT / 128), 256, gemm_smem>>>(
        xr, wqkvH, bqkvS, qkv_ptr, MTOT, C3, CH);
    // Flash attention
    flash_fp16<<<dim3(SEQ / 128, BATCH * NHEADS), 128, flash_smem>>>();
    // Output projection (fp32 output)
    gemm_fp16<false><<<dim3(CH / 128, MTOT / 128), 256, gemm_smem>>>(
        att_ptr, wprojH, bproj, out, MTOT, CH, CH);
}

// round 15
// speedup vs baseline: 1.0244x; 1.0244x over previous
#include <cuda_runtime.h>
#include <cuda_fp16.h>
#include <cstdint>
#include <math.h>

#define BATCH 4
#define SEQ 2048
#define CH 768
#define NHEADS 12
#define HD 64
#define MTOT (BATCH * SEQ)   // 8192
#define C3 (3 * CH)          // 2304
#define KSCALE (0.125f * 1.44269504089f)   // 1/sqrt(d) * log2(e)

// Scratch (allocation-free contract) — all fp16
__device__ __half g_x[(size_t)MTOT * CH];
__device__ __half g_qkv[(size_t)MTOT * C3];
__device__ __half g_att[(size_t)MTOT * CH];
__device__ __half g_wqkvT[(size_t)C3 * CH];    // Wqkv^T [N=2304][K=768], Q-rows scaled
__device__ __half g_wprojT[(size_t)CH * CH];   // Wproj^T

__device__ __forceinline__ uint32_t smem_u32(const void* p) {
    uint32_t a;
    asm("{ .reg .u64 t; cvta.to.shared.u64 t, %1; cvt.u32.u64 %0, t; }"
        : "=r"(a) : "l"(p));
    return a;
}
#define CP16(dst, src) \
    asm volatile("cp.async.cg.shared.global [%0], [%1], 16;" \
                 :: "r"(dst), "l"(src) : "memory")
#define CP_COMMIT() asm volatile("cp.async.commit_group;" ::: "memory")
#define CP_WAIT(n)  asm volatile("cp.async.wait_group %0;" :: "n"(n) : "memory")

// m16n8k16 fp16 mma, fp32 accumulate in-place.
__device__ __forceinline__ void mma16(float* c, const unsigned* a,
                                      unsigned b0, unsigned b1) {
    asm volatile(
        "mma.sync.aligned.m16n8k16.row.col.f32.f16.f16.f32 "
        "{%0,%1,%2,%3}, {%4,%5,%6,%7}, {%8,%9}, {%0,%1,%2,%3};"
        : "+f"(c[0]), "+f"(c[1]), "+f"(c[2]), "+f"(c[3])
        : "r"(a[0]), "r"(a[1]), "r"(a[2]), "r"(a[3]), "r"(b0), "r"(b1));
}
__device__ __forceinline__ void ldsm4(unsigned& r0, unsigned& r1,
                                      unsigned& r2, unsigned& r3,
                                      uint32_t addr) {
    asm volatile("ldmatrix.sync.aligned.m8n8.x4.shared.b16 {%0,%1,%2,%3}, [%4];"
                 : "=r"(r0), "=r"(r1), "=r"(r2), "=r"(r3) : "r"(addr));
}
__device__ __forceinline__ void ldsm4t(unsigned& r0, unsigned& r1,
                                       unsigned& r2, unsigned& r3,
                                       uint32_t addr) {
    asm volatile("ldmatrix.sync.aligned.m8n8.x4.trans.shared.b16 {%0,%1,%2,%3}, [%4];"
                 : "=r"(r0), "=r"(r1), "=r"(r2), "=r"(r3) : "r"(addr));
}
__device__ __forceinline__ unsigned packh2(float a, float b) {
    __half2 h = __floats2half2_rn(a, b);
    return *(unsigned*)&h;
}
__device__ __forceinline__ unsigned ex2h2(unsigned x) {
    unsigned r;
    asm("ex2.approx.f16x2 %0, %1;" : "=r"(r) : "r"(x));
    return r;
}
__device__ __forceinline__ float2 h2f2(unsigned x) {
    __half2 h = *(__half2*)&x;
    return __half22float2(h);
}

// ---------------------------------------------------------------------------
// Prepass: round x to fp16
// ---------------------------------------------------------------------------
__global__ __launch_bounds__(256) void round_kernel(
    const float* __restrict__ in, __half* __restrict__ outp)
{
    const int idx = blockIdx.x * 256 + threadIdx.x;
    float4 v = ((const float4*)in)[idx];
    __half2 h0 = __floats2half2_rn(v.x, v.y);
    __half2 h1 = __floats2half2_rn(v.z, v.w);
    uint2 o = { *(unsigned*)&h0, *(unsigned*)&h1 };
    ((uint2*)outp)[idx] = o;
}

// ---------------------------------------------------------------------------
// Weight transpose to fp16: Wt[n][k] = half(W[k][n] * (n < scale_n ? KSCALE : 1))
// ---------------------------------------------------------------------------
__global__ __launch_bounds__(256) void transpose_kernel(
    const float* __restrict__ W, __half* __restrict__ Wt, int R, int Cc,
    int scale_n)
{
    __shared__ float t[32][33];
    const int bx = blockIdx.x * 32, by = blockIdx.y * 32;
    const int x = threadIdx.x & 31, y4 = (threadIdx.x >> 5) * 4;
    #pragma unroll
    for (int j = 0; j < 4; j++)
        t[y4 + j][x] = W[(long)(by + y4 + j) * Cc + bx + x];
    __syncthreads();
    #pragma unroll
    for (int j = 0; j < 4; j++) {
        const int n = bx + y4 + j;
        float v = t[x][y4 + j];
        if (n < scale_n) v *= KSCALE;
        Wt[(long)n * R + by + x] = __float2half_rn(v);
    }
}

// ---------------------------------------------------------------------------
// fp16 mma.sync GEMM + bias (R13 config): C = A @ Bt^T + bias
// Bias cols < scale_n get KSCALE (folds softmax scale into Q portion).
// 128x128 CTA tile, BK=64, 256 threads, 2-stage cp.async, 2 CTAs/SM.
// ---------------------------------------------------------------------------
#define HS 72
#define HTILE (128 * HS)   // halves per operand tile

template <bool HALF_OUT>
__global__ __launch_bounds__(256, 2) void gemm_fp16(
    const __half* __restrict__ A, const __half* __restrict__ Bt,
    const float* __restrict__ bias, void* __restrict__ Cout,
    int M, int N, int K, int scale_n)
{
    extern __shared__ __half hsm[];
    const int tid = threadIdx.x;
    const int lane = tid & 31, wid = tid >> 5;
    const int g = lane >> 2, tq = lane & 3;
    const int wm = (wid & 3) * 32, wn = (wid >> 2) * 64;
    const int bm = blockIdx.y * 128, bn = blockIdx.x * 128;
    const int sr = tid >> 3, sc8 = (tid & 7) * 8;

    const uint32_t sbase = smem_u32(hsm);
    const uint32_t a_base0 = sbase +
        ((wm + (lane & 15)) * HS + (lane >> 4) * 8) * 2;
    const uint32_t b_base0 = sbase + HTILE * 2 +
        ((wn + (lane & 7) + (lane >> 4) * 8) * HS + ((lane >> 3) & 1) * 8) * 2;

    float acc[2][8][4];
    #pragma unroll
    for (int mt = 0; mt < 2; mt++)
        #pragma unroll
        for (int nt = 0; nt < 8; nt++)
            #pragma unroll
            for (int j = 0; j < 4; j++) acc[mt][nt][j] = 0.f;

    const int NK = K / 64;
    auto issue = [&](int kt, int b) {
        __half* As = hsm + b * 2 * HTILE;
        __half* Bs = As + HTILE;
        const int k0 = kt * 64;
        #pragma unroll
        for (int i = 0; i < 4; i++) {
            int r = sr + 32 * i;
            CP16(smem_u32(As + r * HS + sc8),
                 A + (long)(bm + r) * K + k0 + sc8);
            CP16(smem_u32(Bs + r * HS + sc8),
                 Bt + (long)(bn + r) * K + k0 + sc8);
        }
        CP_COMMIT();
    };

    issue(0, 0);
    for (int kt = 0; kt < NK; kt++) {
        const int buf = kt & 1;
        if (kt + 1 < NK) { issue(kt + 1, buf ^ 1); CP_WAIT(1); }
        else             { CP_WAIT(0); }
        __syncthreads();

        const uint32_t a_buf = a_base0 + buf * 2 * HTILE * 2;
        const uint32_t b_buf = b_base0 + buf * 2 * HTILE * 2;
        #pragma unroll
        for (int ks = 0; ks < 4; ks++) {
            unsigned af[2][4];
            ldsm4(af[0][0], af[0][1], af[0][2], af[0][3], a_buf + ks * 32);
            ldsm4(af[1][0], af[1][1], af[1][2], af[1][3],
                  a_buf + 16 * HS * 2 + ks * 32);
            #pragma unroll
            for (int p = 0; p < 4; p++) {
                unsigned b0, b1, c0, c1;
                ldsm4(b0, b1, c0, c1, b_buf + p * 16 * HS * 2 + ks * 32);
                mma16(acc[0][2 * p],     af[0], b0, b1);
                mma16(acc[1][2 * p],     af[1], b0, b1);
                mma16(acc[0][2 * p + 1], af[0], c0, c1);
                mma16(acc[1][2 * p + 1], af[1], c0, c1);
            }
        }
        __syncthreads();
    }

    #pragma unroll
    for (int mt = 0; mt < 2; mt++) {
        const long r0 = bm + wm + mt * 16 + g;
        #pragma unroll
        for (int nt = 0; nt < 8; nt++) {
            const int col = bn + wn + nt * 8 + 2 * tq;
            float bz0 = bias[col], bz1 = bias[col + 1];
            if (col < scale_n)     bz0 *= KSCALE;
            if (col + 1 < scale_n) bz1 *= KSCALE;
            if (HALF_OUT) {
                __half* C = (__half*)Cout;
                __half2 v0 = __floats2half2_rn(acc[mt][nt][0] + bz0,
                                               acc[mt][nt][1] + bz1);
                __half2 v1 = __floats2half2_rn(acc[mt][nt][2] + bz0,
                                               acc[mt][nt][3] + bz1);
                *(__half2*)(C + r0 * N + col)       = v0;
                *(__half2*)(C + (r0 + 8) * N + col) = v1;
            } else {
                float* C = (float*)Cout;
                float2 v0 = { acc[mt][nt][0] + bz0, acc[mt][nt][1] + bz1 };
                float2 v1 = { acc[mt][nt][2] + bz0, acc[mt][nt][3] + bz1 };
                *(float2*)(C + r0 * N + col)       = v0;
                *(float2*)(C + (r0 + 8) * N + col) = v1;
            }
        }
    }
}

// ---------------------------------------------------------------------------
// Flash attention fp16 (R13 config; Q pre-scaled upstream -> pure cp.async):
// Br=128, Bc=64, 128 threads (4 warps), 3 CTAs/SM, 2-stage KV double buffer,
// P in registers, ex2.approx.f16x2 softmax, deferred l reduction.
// Smem (halves, stride 72): Q 128 | K 2x64 | V 2x64 = 55296 B.
// ---------------------------------------------------------------------------
#define QS_OFF 0
#define KS_OFF (128 * HS)
#define VS_OFF (128 * HS + 2 * 64 * HS)
#define KVBUF (64 * HS)
#define FL_HALVES (128 * HS + 4 * 64 * HS)   // 27648 halves = 55296 B
#define NTILES (SEQ / 64)                    // 32

__global__ __launch_bounds__(128, 3) void flash_fp16()
{
    extern __shared__ __half fsm[];
    __half* Qs = fsm + QS_OFF;

    const int tid = threadIdx.x;
    const int lane = tid & 31, w = tid >> 5;
    const int g = lane >> 2, tq = lane & 3;
    const int b = blockIdx.y / NHEADS, h = blockIdx.y % NHEADS;
    const int q0 = blockIdx.x * 128;
    const long rowbase = (long)b * SEQ;

    const uint32_t q_base = smem_u32(Qs) +
        ((w * 32 + (lane & 15)) * HS + (lane >> 4) * 8) * 2;
    const uint32_t k_base = smem_u32(fsm + KS_OFF) +
        (((lane & 7) + (lane >> 4) * 8) * HS + ((lane >> 3) & 1) * 8) * 2;
    const uint32_t v_base = smem_u32(fsm + VS_OFF) +
        (((lane & 7) + ((lane >> 3) & 1) * 8) * HS + (lane >> 4) * 8) * 2;

    // Stage Q: pure cp.async (Q already scaled by KSCALE in the QKV GEMM).
    // Issued as its own group; covered by the first CP_WAIT(0).
    #pragma unroll
    for (int i = 0; i < 8; i++) {
        int idx = tid + 128 * i;
        int r = idx >> 3, c8 = (idx & 7) * 8;
        CP16(smem_u32(Qs + r * HS + c8),
             &g_qkv[(rowbase + q0 + r) * C3 + h * HD + c8]);
    }
    CP_COMMIT();

    auto issue_kv = [&](int t, int bf) {
        __half* Kd = fsm + KS_OFF + bf * KVBUF;
        __half* Vd = fsm + VS_OFF + bf * KVBUF;
        const int k0 = t * 64;
        #pragma unroll
        for (int i = 0; i < 4; i++) {
            int idx = tid + 128 * i;
            int r = idx >> 3, c8 = (idx & 7) * 8;
            long gb = (rowbase + k0 + r) * C3 + h * HD + c8;
            CP16(smem_u32(Kd + r * HS + c8), &g_qkv[gb + CH]);
            CP16(smem_u32(Vd + r * HS + c8), &g_qkv[gb + 2 * CH]);
        }
        CP_COMMIT();
    };

    float o[2][8][4];
    float m_i[2][2], l_p[2][2];
    #pragma unroll
    for (int mt = 0; mt < 2; mt++) {
        m_i[mt][0] = m_i[mt][1] = -1e30f;
        l_p[mt][0] = l_p[mt][1] = 0.f;
        #pragma unroll
        for (int nt = 0; nt < 8; nt++)
            #pragma unroll
            for (int j = 0; j < 4; j++) o[mt][nt][j] = 0.f;
    }

    issue_kv(0, 0);
    for (int t = 0; t < NTILES; t++) {
        const int buf = t & 1;
        CP_WAIT(0);            // Q (t=0) + KV(t) landed
        __syncthreads();       // all warps done reading buf^1 (tile t-1)
        if (t + 1 < NTILES) issue_kv(t + 1, buf ^ 1);   // overlaps compute(t)

        const uint32_t k_buf = k_base + buf * KVBUF * 2;
        const uint32_t v_buf = v_base + buf * KVBUF * 2;

        // S = Q @ K^T
        float s[2][8][4];
        #pragma unroll
        for (int mt = 0; mt < 2; mt++)
            #pragma unroll
            for (int nt = 0; nt < 8; nt++)
                #pragma unroll
                for (int j = 0; j < 4; j++) s[mt][nt][j] = 0.f;
        #pragma unroll
        for (int ks = 0; ks < 4; ks++) {
            unsigned af[2][4];
            ldsm4(af[0][0], af[0][1], af[0][2], af[0][3], q_base + ks * 32);
            ldsm4(af[1][0], af[1][1], af[1][2], af[1][3],
                  q_base + 16 * HS * 2 + ks * 32);
            #pragma unroll
            for (int p = 0; p < 4; p++) {
                unsigned b0, b1, c0, c1;
                ldsm4(b0, b1, c0, c1, k_buf + p * 16 * HS * 2 + ks * 32);
                mma16(s[0][2 * p],     af[0], b0, b1);
                mma16(s[1][2 * p],     af[1], b0, b1);
                mma16(s[0][2 * p + 1], af[0], c0, c1);
                mma16(s[1][2 * p + 1], af[1], c0, c1);
            }
        }

        // Online softmax (base-2): half2-packed ex2 writes PV A-frags.
        unsigned pa[2][4][4];
        #pragma unroll
        for (int mt = 0; mt < 2; mt++) {
            float mx0 = -1e30f, mx1 = -1e30f;
            #pragma unroll
            for (int nt = 0; nt < 8; nt++) {
                mx0 = fmaxf(mx0, fmaxf(s[mt][nt][0], s[mt][nt][1]));
                mx1 = fmaxf(mx1, fmaxf(s[mt][nt][2], s[mt][nt][3]));
            }
            mx0 = fmaxf(mx0, __shfl_xor_sync(0xffffffffu, mx0, 1));
            mx0 = fmaxf(mx0, __shfl_xor_sync(0xffffffffu, mx0, 2));
            mx1 = fmaxf(mx1, __shfl_xor_sync(0xffffffffu, mx1, 1));
            mx1 = fmaxf(mx1, __shfl_xor_sync(0xffffffffu, mx1, 2));
            const float mn0 = fmaxf(m_i[mt][0], mx0), mn1 = fmaxf(m_i[mt][1], mx1);
            const float cr0 = exp2f(m_i[mt][0] - mn0), cr1 = exp2f(m_i[mt][1] - mn1);
            float rs0 = 0.f, rs1 = 0.f;
            #pragma unroll
            for (int j = 0; j < 4; j++) {
                unsigned e0 = ex2h2(packh2(s[mt][2*j][0]   - mn0,
                                           s[mt][2*j][1]   - mn0));
                unsigned e1 = ex2h2(packh2(s[mt][2*j][2]   - mn1,
                                           s[mt][2*j][3]   - mn1));
                unsigned e2 = ex2h2(packh2(s[mt][2*j+1][0] - mn0,
                                           s[mt][2*j+1][1] - mn0));
                unsigned e3 = ex2h2(packh2(s[mt][2*j+1][2] - mn1,
                                           s[mt][2*j+1][3] - mn1));
                pa[mt][j][0] = e0; pa[mt][j][1] = e1;
                pa[mt][j][2] = e2; pa[mt][j][3] = e3;
                float2 f0 = h2f2(e0), f1 = h2f2(e1);
                float2 f2 = h2f2(e2), f3 = h2f2(e3);
                rs0 += (f0.x + f0.y) + (f2.x + f2.y);
                rs1 += (f1.x + f1.y) + (f3.x + f3.y);
            }
            l_p[mt][0] = l_p[mt][0] * cr0 + rs0;
            l_p[mt][1] = l_p[mt][1] * cr1 + rs1;
            m_i[mt][0] = mn0; m_i[mt][1] = mn1;
            #pragma unroll
            for (int nt = 0; nt < 8; nt++) {
                o[mt][nt][0] *= cr0; o[mt][nt][1] *= cr0;
                o[mt][nt][2] *= cr1; o[mt][nt][3] *= cr1;
            }
        }

        // O += P @ V  (P from registers; V via ldmatrix.trans)
        #pragma unroll
        for (int ks = 0; ks < 4; ks++) {
            #pragma unroll
            for (int p = 0; p < 4; p++) {
                unsigned b0, b1, c0, c1;
                ldsm4t(b0, b1, c0, c1,
                       v_buf + ks * 16 * HS * 2 + p * 16 * 2);
                mma16(o[0][2 * p],     pa[0][ks], b0, b1);
                mma16(o[1][2 * p],     pa[1][ks], b0, b1);
                mma16(o[0][2 * p + 1], pa[0][ks], c0, c1);
                mma16(o[1][2 * p + 1], pa[1][ks], c0, c1);
            }
        }
    }

    // Epilogue: quad-reduce l partials, normalize, store fp16.
    #pragma unroll
    for (int mt = 0; mt < 2; mt++) {
        float l0 = l_p[mt][0], l1 = l_p[mt][1];
        l0 += __shfl_xor_sync(0xffffffffu, l0, 1);
        l0 += __shfl_xor_sync(0xffffffffu, l0, 2);
        l1 += __shfl_xor_sync(0xffffffffu, l1, 1);
        l1 += __shfl_xor_sync(0xffffffffu, l1, 2);
        const float inv0 = 1.f / l0, inv1 = 1.f / l1;
        const long r0 = rowbase + q0 + w * 32 + mt * 16 + g;
        #pragma unroll
        for (int nt = 0; nt < 8; nt++) {
            const int col = h * HD + nt * 8 + 2 * tq;
            *(__half2*)(g_att + r0 * CH + col) =
                __floats2half2_rn(o[mt][nt][0] * inv0, o[mt][nt][1] * inv0);
            *(__half2*)(g_att + (r0 + 8) * CH + col) =
                __floats2half2_rn(o[mt][nt][2] * inv1, o[mt][nt][3] * inv1);
        }
    }
}

// ---------------------------------------------------------------------------
extern "C" void kernel_launch(void* const* d_in, const int* in_sizes, int n_in,
                              void* d_out, int out_size)
{
    const float* x     = (const float*)d_in[0];
    const float* Wqkv  = (const float*)d_in[1];
    const float* bqkv  = (const float*)d_in[2];
    const float* Wproj = (const float*)d_in[3];
    const float* bproj = (const float*)d_in[4];
    float* out = (float*)d_out;

    __half *xr, *qkv_ptr, *att_ptr, *wqkvT, *wprojT;
    cudaGetSymbolAddress((void**)&xr, g_x);
    cudaGetSymbolAddress((void**)&qkv_ptr, g_qkv);
    cudaGetSymbolAddress((void**)&att_ptr, g_att);
    cudaGetSymbolAddress((void**)&wqkvT, g_wqkvT);
    cudaGetSymbolAddress((void**)&wprojT, g_wprojT);

    static int smem_set = 0;
    const int gemm_smem  = 4 * HTILE * sizeof(__half);    // 73728 B
    const int flash_smem = FL_HALVES * sizeof(__half);    // 55296 B
    if (!smem_set) {
        cudaFuncSetAttribute(gemm_fp16<true>,
            cudaFuncAttributeMaxDynamicSharedMemorySize, gemm_smem);
        cudaFuncSetAttribute(gemm_fp16<false>,
            cudaFuncAttributeMaxDynamicSharedMemorySize, gemm_smem);
        cudaFuncSetAttribute(flash_fp16,
            cudaFuncAttributeMaxDynamicSharedMemorySize, flash_smem);
        smem_set = 1;
    }

    // Prepasses: x -> fp16; weights -> fp16 transposed
    // (Wqkv Q-rows scaled by KSCALE during transpose; no extra kernel).
    round_kernel<<<(MTOT * CH) / 1024, 256>>>(x, xr);
    transpose_kernel<<<dim3(C3 / 32, CH / 32), 256>>>(Wqkv, wqkvT, CH, C3, CH);
    transpose_kernel<<<dim3(CH / 32, CH / 32), 256>>>(Wproj, wprojT, CH, CH, 0);

    // QKV projection (fp16 output; Q cols scaled, incl. bias in epilogue)
    gemm_fp16<true><<<dim3(C3 / 128, MTOT / 128), 256, gemm_smem>>>(
        xr, wqkvT, bqkv, qkv_ptr, MTOT, C3, CH, CH);
    // Flash attention (3 CTAs/SM, double-buffered KV, P in regs, f16x2 exp)
    flash_fp16<<<dim3(SEQ / 128, BATCH * NHEADS), 128, flash_smem>>>();
    // Output projection (fp32 output)
    gemm_fp16<false><<<dim3(CH / 128, MTOT / 128), 256, gemm_smem>>>(
        att_ptr, wprojT, bproj, out, MTOT, CH, CH, 0);
}

// round 16
// speedup vs baseline: 1.0257x; 1.0013x over previous
#include <cuda_runtime.h>
#include <cuda_fp16.h>
#include <cstdint>
#include <math.h>

#define BATCH 4
#define SEQ 2048
#define CH 768
#define NHEADS 12
#define HD 64
#define MTOT (BATCH * SEQ)   // 8192
#define C3 (3 * CH)          // 2304
#define KSCALE (0.125f * 1.44269504089f)   // 1/sqrt(d) * log2(e)

// Scratch (allocation-free contract) — all fp16
__device__ __half g_x[(size_t)MTOT * CH];
__device__ __half g_qkv[(size_t)MTOT * C3];
__device__ __half g_att[(size_t)MTOT * CH];
__device__ __half g_wqkvT[(size_t)C3 * CH];    // Wqkv^T, Q-rows scaled
__device__ __half g_wprojT[(size_t)CH * CH];   // Wproj^T

__device__ __forceinline__ uint32_t smem_u32(const void* p) {
    uint32_t a;
    asm("{ .reg .u64 t; cvta.to.shared.u64 t, %1; cvt.u32.u64 %0, t; }"
        : "=r"(a) : "l"(p));
    return a;
}
#define CP16(dst, src) \
    asm volatile("cp.async.cg.shared.global [%0], [%1], 16;" \
                 :: "r"(dst), "l"(src) : "memory")
#define CP_COMMIT() asm volatile("cp.async.commit_group;" ::: "memory")
#define CP_WAIT(n)  asm volatile("cp.async.wait_group %0;" :: "n"(n) : "memory")

// m16n8k16 fp16 mma, fp32 accumulate in-place.
__device__ __forceinline__ void mma16(float* c, const unsigned* a,
                                      unsigned b0, unsigned b1) {
    asm volatile(
        "mma.sync.aligned.m16n8k16.row.col.f32.f16.f16.f32 "
        "{%0,%1,%2,%3}, {%4,%5,%6,%7}, {%8,%9}, {%0,%1,%2,%3};"
        : "+f"(c[0]), "+f"(c[1]), "+f"(c[2]), "+f"(c[3])
        : "r"(a[0]), "r"(a[1]), "r"(a[2]), "r"(a[3]), "r"(b0), "r"(b1));
}
__device__ __forceinline__ void ldsm4(unsigned& r0, unsigned& r1,
                                      unsigned& r2, unsigned& r3,
                                      uint32_t addr) {
    asm volatile("ldmatrix.sync.aligned.m8n8.x4.shared.b16 {%0,%1,%2,%3}, [%4];"
                 : "=r"(r0), "=r"(r1), "=r"(r2), "=r"(r3) : "r"(addr));
}
__device__ __forceinline__ void ldsm4t(unsigned& r0, unsigned& r1,
                                       unsigned& r2, unsigned& r3,
                                       uint32_t addr) {
    asm volatile("ldmatrix.sync.aligned.m8n8.x4.trans.shared.b16 {%0,%1,%2,%3}, [%4];"
                 : "=r"(r0), "=r"(r1), "=r"(r2), "=r"(r3) : "r"(addr));
}
__device__ __forceinline__ unsigned packh2(float a, float b) {
    __half2 h = __floats2half2_rn(a, b);
    return *(unsigned*)&h;
}
__device__ __forceinline__ unsigned ex2h2(unsigned x) {
    unsigned r;
    asm("ex2.approx.f16x2 %0, %1;" : "=r"(r) : "r"(x));
    return r;
}
__device__ __forceinline__ float2 h2f2(unsigned x) {
    __half2 h = *(__half2*)&x;
    return __half22float2(h);
}

// ---------------------------------------------------------------------------
// Fused prepass: ONE launch does
//   [0, NB_ROUND)            round x -> fp16
//   [NB_ROUND, +NB_T1)       transpose+round Wqkv (Q-rows scaled by KSCALE)
//   [.., +NB_T2)             transpose+round Wproj
// ---------------------------------------------------------------------------
#define NB_ROUND ((MTOT * CH) / 1024)          // 6144
#define NB_T1 ((C3 / 32) * (CH / 32))          // 1728
#define NB_T2 ((CH / 32) * (CH / 32))          // 576
#define NB_PREP (NB_ROUND + NB_T1 + NB_T2)

__device__ __forceinline__ void transpose_tile(
    const float* __restrict__ W, __half* __restrict__ Wt,
    int R, int Cc, int scale_n, int bx, int by, float tbuf[32][33])
{
    const int x = threadIdx.x & 31, y4 = (threadIdx.x >> 5) * 4;
    #pragma unroll
    for (int j = 0; j < 4; j++)
        tbuf[y4 + j][x] = W[(long)(by + y4 + j) * Cc + bx + x];
    __syncthreads();
    #pragma unroll
    for (int j = 0; j < 4; j++) {
        const int n = bx + y4 + j;
        float v = tbuf[x][y4 + j];
        if (n < scale_n) v *= KSCALE;
        Wt[(long)n * R + by + x] = __float2half_rn(v);
    }
}

__global__ __launch_bounds__(256) void prep_kernel(
    const float* __restrict__ x, __half* __restrict__ xr,
    const float* __restrict__ Wqkv, __half* __restrict__ wqkvT,
    const float* __restrict__ Wproj, __half* __restrict__ wprojT)
{
    __shared__ float tbuf[32][33];
    const int bid = blockIdx.x;
    if (bid < NB_ROUND) {
        const int idx = bid * 256 + threadIdx.x;
        float4 v = ((const float4*)x)[idx];
        __half2 h0 = __floats2half2_rn(v.x, v.y);
        __half2 h1 = __floats2half2_rn(v.z, v.w);
        uint2 o = { *(unsigned*)&h0, *(unsigned*)&h1 };
        ((uint2*)xr)[idx] = o;
    } else if (bid < NB_ROUND + NB_T1) {
        const int tb = bid - NB_ROUND;
        transpose_tile(Wqkv, wqkvT, CH, C3, CH,
                       (tb % (C3 / 32)) * 32, (tb / (C3 / 32)) * 32, tbuf);
    } else {
        const int tb = bid - NB_ROUND - NB_T1;
        transpose_tile(Wproj, wprojT, CH, CH, 0,
                       (tb % (CH / 32)) * 32, (tb / (CH / 32)) * 32, tbuf);
    }
}

// ---------------------------------------------------------------------------
// fp16 mma.sync GEMM + bias: C = A @ Bt^T + bias  (bias cols < scale_n scaled)
// 128x128 CTA tile, BK=64, 256 threads, 2-stage cp.async, 2 CTAs/SM.
// ---------------------------------------------------------------------------
#define HS 72
#define HTILE (128 * HS)

template <bool HALF_OUT>
__global__ __launch_bounds__(256, 2) void gemm_fp16(
    const __half* __restrict__ A, const __half* __restrict__ Bt,
    const float* __restrict__ bias, void* __restrict__ Cout,
    int M, int N, int K, int scale_n)
{
    extern __shared__ __half hsm[];
    const int tid = threadIdx.x;
    const int lane = tid & 31, wid = tid >> 5;
    const int g = lane >> 2, tq = lane & 3;
    const int wm = (wid & 3) * 32, wn = (wid >> 2) * 64;
    const int bm = blockIdx.y * 128, bn = blockIdx.x * 128;
    const int sr = tid >> 3, sc8 = (tid & 7) * 8;

    const uint32_t sbase = smem_u32(hsm);
    const uint32_t a_base0 = sbase +
        ((wm + (lane & 15)) * HS + (lane >> 4) * 8) * 2;
    const uint32_t b_base0 = sbase + HTILE * 2 +
        ((wn + (lane & 7) + (lane >> 4) * 8) * HS + ((lane >> 3) & 1) * 8) * 2;

    float acc[2][8][4];
    #pragma unroll
    for (int mt = 0; mt < 2; mt++)
        #pragma unroll
        for (int nt = 0; nt < 8; nt++)
            #pragma unroll
            for (int j = 0; j < 4; j++) acc[mt][nt][j] = 0.f;

    const int NK = K / 64;
    auto issue = [&](int kt, int b) {
        __half* As = hsm + b * 2 * HTILE;
        __half* Bs = As + HTILE;
        const int k0 = kt * 64;
        #pragma unroll
        for (int i = 0; i < 4; i++) {
            int r = sr + 32 * i;
            CP16(smem_u32(As + r * HS + sc8),
                 A + (long)(bm + r) * K + k0 + sc8);
            CP16(smem_u32(Bs + r * HS + sc8),
                 Bt + (long)(bn + r) * K + k0 + sc8);
        }
        CP_COMMIT();
    };

    issue(0, 0);
    for (int kt = 0; kt < NK; kt++) {
        const int buf = kt & 1;
        if (kt + 1 < NK) { issue(kt + 1, buf ^ 1); CP_WAIT(1); }
        else             { CP_WAIT(0); }
        __syncthreads();

        const uint32_t a_buf = a_base0 + buf * 2 * HTILE * 2;
        const uint32_t b_buf = b_base0 + buf * 2 * HTILE * 2;
        #pragma unroll
        for (int ks = 0; ks < 4; ks++) {
            unsigned af[2][4];
            ldsm4(af[0][0], af[0][1], af[0][2], af[0][3], a_buf + ks * 32);
            ldsm4(af[1][0], af[1][1], af[1][2], af[1][3],
                  a_buf + 16 * HS * 2 + ks * 32);
            #pragma unroll
            for (int p = 0; p < 4; p++) {
                unsigned b0, b1, c0, c1;
                ldsm4(b0, b1, c0, c1, b_buf + p * 16 * HS * 2 + ks * 32);
                mma16(acc[0][2 * p],     af[0], b0, b1);
                mma16(acc[1][2 * p],     af[1], b0, b1);
                mma16(acc[0][2 * p + 1], af[0], c0, c1);
                mma16(acc[1][2 * p + 1], af[1], c0, c1);
            }
        }
        __syncthreads();
    }

    #pragma unroll
    for (int mt = 0; mt < 2; mt++) {
        const long r0 = bm + wm + mt * 16 + g;
        #pragma unroll
        for (int nt = 0; nt < 8; nt++) {
            const int col = bn + wn + nt * 8 + 2 * tq;
            float bz0 = bias[col], bz1 = bias[col + 1];
            if (col < scale_n)     bz0 *= KSCALE;
            if (col + 1 < scale_n) bz1 *= KSCALE;
            if (HALF_OUT) {
                __half* C = (__half*)Cout;
                __half2 v0 = __floats2half2_rn(acc[mt][nt][0] + bz0,
                                               acc[mt][nt][1] + bz1);
                __half2 v1 = __floats2half2_rn(acc[mt][nt][2] + bz0,
                                               acc[mt][nt][3] + bz1);
                *(__half2*)(C + r0 * N + col)       = v0;
                *(__half2*)(C + (r0 + 8) * N + col) = v1;
            } else {
                float* C = (float*)Cout;
                float2 v0 = { acc[mt][nt][0] + bz0, acc[mt][nt][1] + bz1 };
                float2 v1 = { acc[mt][nt][2] + bz0, acc[mt][nt][3] + bz1 };
                *(float2*)(C + r0 * N + col)       = v0;
                *(float2*)(C + (r0 + 8) * N + col) = v1;
            }
        }
    }
}

// ---------------------------------------------------------------------------
// Flash attention fp16: Br=128, Bc=64, 128 threads (4 warps), 3 CTAs/SM,
// 2-stage KV, P in registers, ex2.approx.f16x2 softmax, deferred l
// reduction, warp-voted o-rescale skip when the running max is stable.
// Smem (halves, stride 72): Q 128 | K 2x64 | V 2x64 = 55296 B.
// ---------------------------------------------------------------------------
#define QS_OFF 0
#define KS_OFF (128 * HS)
#define VS_OFF (128 * HS + 2 * 64 * HS)
#define KVBUF (64 * HS)
#define FL_HALVES (128 * HS + 4 * 64 * HS)   // 55296 B
#define NTILES (SEQ / 64)                    // 32

__global__ __launch_bounds__(128, 3) void flash_fp16()
{
    extern __shared__ __half fsm[];
    __half* Qs = fsm + QS_OFF;

    const int tid = threadIdx.x;
    const int lane = tid & 31, w = tid >> 5;
    const int g = lane >> 2, tq = lane & 3;
    const int b = blockIdx.y / NHEADS, h = blockIdx.y % NHEADS;
    const int q0 = blockIdx.x * 128;
    const long rowbase = (long)b * SEQ;

    const uint32_t q_base = smem_u32(Qs) +
        ((w * 32 + (lane & 15)) * HS + (lane >> 4) * 8) * 2;
    const uint32_t k_base = smem_u32(fsm + KS_OFF) +
        (((lane & 7) + (lane >> 4) * 8) * HS + ((lane >> 3) & 1) * 8) * 2;
    const uint32_t v_base = smem_u32(fsm + VS_OFF) +
        (((lane & 7) + ((lane >> 3) & 1) * 8) * HS + (lane >> 4) * 8) * 2;

    // Stage Q: pure cp.async (Q pre-scaled in the QKV GEMM).
    #pragma unroll
    for (int i = 0; i < 8; i++) {
        int idx = tid + 128 * i;
        int r = idx >> 3, c8 = (idx & 7) * 8;
        CP16(smem_u32(Qs + r * HS + c8),
             &g_qkv[(rowbase + q0 + r) * C3 + h * HD + c8]);
    }
    CP_COMMIT();

    auto issue_kv = [&](int t, int bf) {
        __half* Kd = fsm + KS_OFF + bf * KVBUF;
        __half* Vd = fsm + VS_OFF + bf * KVBUF;
        const int k0 = t * 64;
        #pragma unroll
        for (int i = 0; i < 4; i++) {
            int idx = tid + 128 * i;
            int r = idx >> 3, c8 = (idx & 7) * 8;
            long gb = (rowbase + k0 + r) * C3 + h * HD + c8;
            CP16(smem_u32(Kd + r * HS + c8), &g_qkv[gb + CH]);
            CP16(smem_u32(Vd + r * HS + c8), &g_qkv[gb + 2 * CH]);
        }
        CP_COMMIT();
    };

    float o[2][8][4];
    float m_i[2][2], l_p[2][2];
    #pragma unroll
    for (int mt = 0; mt < 2; mt++) {
        m_i[mt][0] = m_i[mt][1] = -1e30f;
        l_p[mt][0] = l_p[mt][1] = 0.f;
        #pragma unroll
        for (int nt = 0; nt < 8; nt++)
            #pragma unroll
            for (int j = 0; j < 4; j++) o[mt][nt][j] = 0.f;
    }

    issue_kv(0, 0);
    for (int t = 0; t < NTILES; t++) {
        const int buf = t & 1;
        CP_WAIT(0);
        __syncthreads();
        if (t + 1 < NTILES) issue_kv(t + 1, buf ^ 1);

        const uint32_t k_buf = k_base + buf * KVBUF * 2;
        const uint32_t v_buf = v_base + buf * KVBUF * 2;

        // S = Q @ K^T
        float s[2][8][4];
        #pragma unroll
        for (int mt = 0; mt < 2; mt++)
            #pragma unroll
            for (int nt = 0; nt < 8; nt++)
                #pragma unroll
                for (int j = 0; j < 4; j++) s[mt][nt][j] = 0.f;
        #pragma unroll
        for (int ks = 0; ks < 4; ks++) {
            unsigned af[2][4];
            ldsm4(af[0][0], af[0][1], af[0][2], af[0][3], q_base + ks * 32);
            ldsm4(af[1][0], af[1][1], af[1][2], af[1][3],
                  q_base + 16 * HS * 2 + ks * 32);
            #pragma unroll
            for (int p = 0; p < 4; p++) {
                unsigned b0, b1, c0, c1;
                ldsm4(b0, b1, c0, c1, k_buf + p * 16 * HS * 2 + ks * 32);
                mma16(s[0][2 * p],     af[0], b0, b1);
                mma16(s[1][2 * p],     af[1], b0, b1);
                mma16(s[0][2 * p + 1], af[0], c0, c1);
                mma16(s[1][2 * p + 1], af[1], c0, c1);
            }
        }

        // Online softmax (base-2): half2-packed ex2 writes PV A-frags.
        unsigned pa[2][4][4];
        #pragma unroll
        for (int mt = 0; mt < 2; mt++) {
            float mx0 = -1e30f, mx1 = -1e30f;
            #pragma unroll
            for (int nt = 0; nt < 8; nt++) {
                mx0 = fmaxf(mx0, fmaxf(s[mt][nt][0], s[mt][nt][1]));
                mx1 = fmaxf(mx1, fmaxf(s[mt][nt][2], s[mt][nt][3]));
            }
            mx0 = fmaxf(mx0, __shfl_xor_sync(0xffffffffu, mx0, 1));
            mx0 = fmaxf(mx0, __shfl_xor_sync(0xffffffffu, mx0, 2));
            mx1 = fmaxf(mx1, __shfl_xor_sync(0xffffffffu, mx1, 1));
            mx1 = fmaxf(mx1, __shfl_xor_sync(0xffffffffu, mx1, 2));
            const float mn0 = fmaxf(m_i[mt][0], mx0), mn1 = fmaxf(m_i[mt][1], mx1);
            const float cr0 = exp2f(m_i[mt][0] - mn0), cr1 = exp2f(m_i[mt][1] - mn1);
            float rs0 = 0.f, rs1 = 0.f;
            #pragma unroll
            for (int j = 0; j < 4; j++) {
                unsigned e0 = ex2h2(packh2(s[mt][2*j][0]   - mn0,
                                           s[mt][2*j][1]   - mn0));
                unsigned e1 = ex2h2(packh2(s[mt][2*j][2]   - mn1,
                                           s[mt][2*j][3]   - mn1));
                unsigned e2 = ex2h2(packh2(s[mt][2*j+1][0] - mn0,
                                           s[mt][2*j+1][1] - mn0));
                unsigned e3 = ex2h2(packh2(s[mt][2*j+1][2] - mn1,
                                           s[mt][2*j+1][3] - mn1));
                pa[mt][j][0] = e0; pa[mt][j][1] = e1;
                pa[mt][j][2] = e2; pa[mt][j][3] = e3;
                float2 f0 = h2f2(e0), f1 = h2f2(e1);
                float2 f2 = h2f2(e2), f3 = h2f2(e3);
                rs0 += (f0.x + f0.y) + (f2.x + f2.y);
                rs1 += (f1.x + f1.y) + (f3.x + f3.y);
            }
            l_p[mt][0] = l_p[mt][0] * cr0 + rs0;
            l_p[mt][1] = l_p[mt][1] * cr1 + rs1;
            m_i[mt][0] = mn0; m_i[mt][1] = mn1;
            // Warp-voted rescale skip: cr==1.0 exactly when max unchanged
            // (ex2(0)=1); multiplying by 1.0 is a no-op, so skipping is
            // bit-exact. Vote keeps the warp convergent.
            if (!__all_sync(0xffffffffu, (cr0 == 1.f) && (cr1 == 1.f))) {
                #pragma unroll
                for (int nt = 0; nt < 8; nt++) {
                    o[mt][nt][0] *= cr0; o[mt][nt][1] *= cr0;
                    o[mt][nt][2] *= cr1; o[mt][nt][3] *= cr1;
                }
            }
        }

        // O += P @ V  (P from registers; V via ldmatrix.trans)
        #pragma unroll
        for (int ks = 0; ks < 4; ks++) {
            #pragma unroll
            for (int p = 0; p < 4; p++) {
                unsigned b0, b1, c0, c1;
                ldsm4t(b0, b1, c0, c1,
                       v_buf + ks * 16 * HS * 2 + p * 16 * 2);
                mma16(o[0][2 * p],     pa[0][ks], b0, b1);
                mma16(o[1][2 * p],     pa[1][ks], b0, b1);
                mma16(o[0][2 * p + 1], pa[0][ks], c0, c1);
                mma16(o[1][2 * p + 1], pa[1][ks], c0, c1);
            }
        }
    }

    // Epilogue: quad-reduce l partials, normalize, store fp16.
    #pragma unroll
    for (int mt = 0; mt < 2; mt++) {
        float l0 = l_p[mt][0], l1 = l_p[mt][1];
        l0 += __shfl_xor_sync(0xffffffffu, l0, 1);
        l0 += __shfl_xor_sync(0xffffffffu, l0, 2);
        l1 += __shfl_xor_sync(0xffffffffu, l1, 1);
        l1 += __shfl_xor_sync(0xffffffffu, l1, 2);
        const float inv0 = 1.f / l0, inv1 = 1.f / l1;
        const long r0 = rowbase + q0 + w * 32 + mt * 16 + g;
        #pragma unroll
        for (int nt = 0; nt < 8; nt++) {
            const int col = h * HD + nt * 8 + 2 * tq;
            *(__half2*)(g_att + r0 * CH + col) =
                __floats2half2_rn(o[mt][nt][0] * inv0, o[mt][nt][1] * inv0);
            *(__half2*)(g_att + (r0 + 8) * CH + col) =
                __floats2half2_rn(o[mt][nt][2] * inv1, o[mt][nt][3] * inv1);
        }
    }
}

// ---------------------------------------------------------------------------
extern "C" void kernel_launch(void* const* d_in, const int* in_sizes, int n_in,
                              void* d_out, int out_size)
{
    const float* x     = (const float*)d_in[0];
    const float* Wqkv  = (const float*)d_in[1];
    const float* bqkv  = (const float*)d_in[2];
    const float* Wproj = (const float*)d_in[3];
    const float* bproj = (const float*)d_in[4];
    float* out = (float*)d_out;

    __half *xr, *qkv_ptr, *att_ptr, *wqkvT, *wprojT;
    cudaGetSymbolAddress((void**)&xr, g_x);
    cudaGetSymbolAddress((void**)&qkv_ptr, g_qkv);
    cudaGetSymbolAddress((void**)&att_ptr, g_att);
    cudaGetSymbolAddress((void**)&wqkvT, g_wqkvT);
    cudaGetSymbolAddress((void**)&wprojT, g_wprojT);

    static int smem_set = 0;
    const int gemm_smem  = 4 * HTILE * sizeof(__half);    // 73728 B
    const int flash_smem = FL_HALVES * sizeof(__half);    // 55296 B
    if (!smem_set) {
        cudaFuncSetAttribute(gemm_fp16<true>,
            cudaFuncAttributeMaxDynamicSharedMemorySize, gemm_smem);
        cudaFuncSetAttribute(gemm_fp16<false>,
            cudaFuncAttributeMaxDynamicSharedMemorySize, gemm_smem);
        cudaFuncSetAttribute(flash_fp16,
            cudaFuncAttributeMaxDynamicSharedMemorySize, flash_smem);
        smem_set = 1;
    }

    // Fused prepass (x round + both weight transposes) in ONE launch
    prep_kernel<<<NB_PREP, 256>>>(x, xr, Wqkv, wqkvT, Wproj, wprojT);

    // QKV projection (fp16 output; Q cols + bias scaled by KSCALE)
    gemm_fp16<true><<<dim3(C3 / 128, MTOT / 128), 256, gemm_smem>>>(
        xr, wqkvT, bqkv, qkv_ptr, MTOT, C3, CH, CH);
    // Flash attention
    flash_fp16<<<dim3(SEQ / 128, BATCH * NHEADS), 128, flash_smem>>>();
    // Output projection (fp32 output)
    gemm_fp16<false><<<dim3(CH / 128, MTOT / 128), 256, gemm_smem>>>(
        att_ptr, wprojT, bproj, out, MTOT, CH, CH, 0);
}